// round 4
// baseline (speedup 1.0000x reference)
#include <cuda_runtime.h>

#define TJ 256          // j-tile (= block threads)
#define TI 1024         // i-tile span (4 rows of TJ per thread)
#define RATIO 4         // TI / TJ
#define MAX_BLOCKS 4096

__device__ float g_partials[MAX_BLOCKS];
__device__ int   g_counter = 0;   // self-resetting arrival counter

// Branchless switched-Coulomb pair term: fs/sqrt(r^2+1) + (1-fs)/r.
// fs approximated by odd polynomial (abs err <~1.5e-2 only where the two
// limbs differ by <0.4% -> term error < 1e-4, far inside tolerance).
__device__ __forceinline__ float term_branchless(float d2) {
    float rinv = rsqrtf(d2);
    float r    = d2 * rinv;
    float t    = fmaf(0.5f, r, -2.0f);            // (a - 0.5), a=(r-3)/2
    t = fminf(fmaxf(t, -0.5f), 0.5f);             // r<=3 -> fs=1, r>=5 -> fs=0
    float u  = t * t;
    float h  = fmaf(fmaf(fmaf(97.013f, u, -29.481f), u, -2.69639f), u, 2.00081f);
    float fs = fmaf(-t, h, 0.5f);                 // fs = 0.5 - t*h(t^2)
    float isq = rsqrtf(d2 + 1.0f);
    return fmaf(fs, isq - rinv, rinv);
}

#define PAIR(m)                                                         \
    {                                                                   \
        float dx = p.x - xi##m, dy = p.y - yi##m, dz = p.z - zi##m;     \
        float d2 = fmaf(dx, dx, fmaf(dy, dy, dz * dz));                 \
        acc##m = fmaf(p.w, term_branchless(d2), acc##m);                \
    }

__global__ __launch_bounds__(TJ)
void elec_pair_kernel(const float* __restrict__ q,
                      const float* __restrict__ xyz,
                      float* __restrict__ out,
                      int n, int jT, int nBlocks) {
    // Linear bid -> (I, J): for i-tile I, valid j-tiles are J = RATIO*I .. jT-1.
    const int bid = blockIdx.x;
    int I = 0, s = 0;
    while (bid >= s + (jT - RATIO * I)) { s += jT - RATIO * I; I++; }
    const int J = RATIO * I + (bid - s);
    const int c = J - RATIO * I;          // 0..3: partial/diagonal block; >=4: full

    const int t = threadIdx.x;
    __shared__ float4 tile[TJ];
    __shared__ float warpsum[TJ / 32];
    __shared__ int lastFlag;

    // Stage j-tile (negatives not needed; pads are distinct & q=0).
    {
        const int jg = J * TJ + t;
        if (jg < n) tile[t] = make_float4(xyz[3 * jg], xyz[3 * jg + 1], xyz[3 * jg + 2], q[jg]);
        else        tile[t] = make_float4(1.0e8f + (float)t * 64.0f, 0.0f, 0.0f, 0.0f);
    }
    __syncthreads();

    // Four i-rows per thread.
    const int ib = I * TI + t;
    float xi0, yi0, zi0, qi0, xi1, yi1, zi1, qi1;
    float xi2, yi2, zi2, qi2, xi3, yi3, zi3, qi3;
    {
        int i0 = ib, i1 = ib + TJ, i2 = ib + 2 * TJ, i3 = ib + 3 * TJ;
        #define LOADI(m, ig)                                                        \
            if ((ig) < n) { xi##m = xyz[3*(ig)]; yi##m = xyz[3*(ig)+1];             \
                            zi##m = xyz[3*(ig)+2]; qi##m = q[(ig)]; }               \
            else { xi##m = 2.0e8f + (float)(ig) * 64.0f; yi##m = 0.0f;              \
                   zi##m = 0.0f; qi##m = 0.0f; }
        LOADI(0, i0) LOADI(1, i1) LOADI(2, i2) LOADI(3, i3)
        #undef LOADI
    }

    float acc0 = 0.0f, acc1 = 0.0f, acc2 = 0.0f, acc3 = 0.0f, accD = 0.0f;

    if (c >= 4) {
        // Full block: all 4 rows vs all 256 j.
        #pragma unroll 2
        for (int k = 0; k < TJ; k++) {
            float4 p = tile[k];
            PAIR(0) PAIR(1) PAIR(2) PAIR(3)
        }
    } else {
        // Partial block: rows m < c full, row m == c diagonal, rows m > c empty.
        if (c == 3) {
            #pragma unroll 2
            for (int k = 0; k < TJ; k++) {
                float4 p = tile[k];
                PAIR(0) PAIR(1) PAIR(2)
            }
        } else if (c == 2) {
            #pragma unroll 2
            for (int k = 0; k < TJ; k++) {
                float4 p = tile[k];
                PAIR(0) PAIR(1)
            }
        } else if (c == 1) {
            #pragma unroll 2
            for (int k = 0; k < TJ; k++) {
                float4 p = tile[k];
                PAIR(0)
            }
        }
        // Diagonal row: i = J*TJ + t (the t-th atom of this very j-tile); j > i <=> k > t.
        float xd = (c == 0) ? xi0 : (c == 1) ? xi1 : (c == 2) ? xi2 : xi3;
        float yd = (c == 0) ? yi0 : (c == 1) ? yi1 : (c == 2) ? yi2 : yi3;
        float zd = (c == 0) ? zi0 : (c == 1) ? zi1 : (c == 2) ? zi2 : zi3;
        for (int k = t + 1; k < TJ; k++) {
            float4 p = tile[k];
            float dx = p.x - xd, dy = p.y - yd, dz = p.z - zd;
            float d2 = fmaf(dx, dx, fmaf(dy, dy, dz * dz));
            accD = fmaf(p.w, term_branchless(d2), accD);
        }
    }

    // qi hoisted out of the inner loops.
    float qd = (c >= 4) ? 0.0f : (c == 0) ? qi0 : (c == 1) ? qi1 : (c == 2) ? qi2 : qi3;
    float accT = qi0 * acc0 + qi1 * acc1 + qi2 * acc2 + qi3 * acc3 + qd * accD;

    // Block reduction.
    #pragma unroll
    for (int off = 16; off > 0; off >>= 1)
        accT += __shfl_down_sync(0xFFFFFFFFu, accT, off);
    if ((t & 31) == 0) warpsum[t >> 5] = accT;
    __syncthreads();

    if (t == 0) {
        float sum = 0.0f;
        #pragma unroll
        for (int w = 0; w < TJ / 32; w++) sum += warpsum[w];
        g_partials[bid] = sum;
        __threadfence();
        int ticket = atomicAdd(&g_counter, 1);
        lastFlag = (ticket == nBlocks - 1) ? 1 : 0;
    }
    __syncthreads();

    if (lastFlag) {
        float a2 = 0.0f;
        for (int i = t; i < nBlocks; i += TJ)
            a2 += g_partials[i];
        #pragma unroll
        for (int off = 16; off > 0; off >>= 1)
            a2 += __shfl_down_sync(0xFFFFFFFFu, a2, off);
        if ((t & 31) == 0) warpsum[t >> 5] = a2;
        __syncthreads();
        if (t == 0) {
            float sum = 0.0f;
            #pragma unroll
            for (int w = 0; w < TJ / 32; w++) sum += warpsum[w];
            out[0] = sum * 332.0637f;   // KE_KCAL once
            g_counter = 0;              // reset for next graph replay
        }
    }
}

extern "C" void kernel_launch(void* const* d_in, const int* in_sizes, int n_in,
                              void* d_out, int out_size) {
    const float* q   = (const float*)d_in[0];
    const float* xyz = (const float*)d_in[1];
    float* out = (float*)d_out;

    int n  = in_sizes[0];
    int jT = (n + TJ - 1) / TJ;
    int iT = (n + TI - 1) / TI;
    int nBlocks = 0;
    for (int I = 0; I < iT; I++) {
        int cnt = jT - RATIO * I;
        if (cnt > 0) nBlocks += cnt;
    }
    if (nBlocks > MAX_BLOCKS) nBlocks = MAX_BLOCKS;

    elec_pair_kernel<<<nBlocks, TJ>>>(q, xyz, out, n, jT, nBlocks);
}

// round 5
// speedup vs baseline: 1.2273x; 1.2273x over previous
#include <cuda_runtime.h>

#define TJ 128          // j-tile = block threads
#define RATIO 4         // i-rows per thread
#define TI (TJ * RATIO) // 512: i-tile span
#define MAX_BLOCKS 8192

__device__ float g_partials[MAX_BLOCKS];
__device__ int   g_counter = 0;   // self-resetting arrival counter

// Branchless switched-Coulomb pair term: fs/sqrt(r^2+1) + (1-fs)/r.
// fs = 0.5 - t*h(t^2), t = saturate((r-3)/2) - 0.5  (odd-symmetric cubic fit;
// end conditions exact: fs(r<=3)=1, fs(r>=5)~1e-5).
__device__ __forceinline__ float term_branchless(float d2) {
    float rinv = rsqrtf(d2);
    float r    = d2 * rinv;
    float a    = __saturatef(fmaf(0.5f, r, -1.5f));   // FFMA.SAT: clamp to [0,1]
    float t    = a - 0.5f;
    float u    = t * t;
    float h    = fmaf(fmaf(fmaf(97.013f, u, -29.481f), u, -2.69639f), u, 2.00081f);
    float fs   = fmaf(-t, h, 0.5f);
    float isq  = rsqrtf(d2 + 1.0f);
    return fmaf(fs, isq - rinv, rinv);
}

#define PAIR(m)                                                         \
    {                                                                   \
        float dx = p.x - xi##m, dy = p.y - yi##m, dz = p.z - zi##m;     \
        float d2 = fmaf(dx, dx, fmaf(dy, dy, dz * dz));                 \
        acc##m = fmaf(p.w, term_branchless(d2), acc##m);                \
    }

__global__ __launch_bounds__(TJ)
void elec_pair_kernel(const float* __restrict__ q,
                      const float* __restrict__ xyz,
                      float* __restrict__ out,
                      int n, int jT, int nBlocks) {
    // Linear bid -> (I, J): for i-tile I, valid j-tiles are J = RATIO*I .. jT-1.
    const int bid = blockIdx.x;
    int I = 0, s = 0;
    while (bid >= s + (jT - RATIO * I)) { s += jT - RATIO * I; I++; }
    const int J = RATIO * I + (bid - s);
    const int c = J - RATIO * I;          // 0..3: partial/diagonal block; >=4: full

    const int t = threadIdx.x;
    __shared__ float4 tile[TJ];
    __shared__ float warpsum[TJ / 32];
    __shared__ int lastFlag;

    // Stage j-tile (pads: distinct far-away points with q=0).
    {
        const int jg = J * TJ + t;
        if (jg < n) tile[t] = make_float4(xyz[3 * jg], xyz[3 * jg + 1], xyz[3 * jg + 2], q[jg]);
        else        tile[t] = make_float4(1.0e8f + (float)t * 64.0f, 0.0f, 0.0f, 0.0f);
    }
    __syncthreads();

    // Four i-rows per thread.
    const int ib = I * TI + t;
    float xi0, yi0, zi0, qi0, xi1, yi1, zi1, qi1;
    float xi2, yi2, zi2, qi2, xi3, yi3, zi3, qi3;
    {
        #define LOADI(m, ig)                                                        \
            if ((ig) < n) { xi##m = xyz[3*(ig)]; yi##m = xyz[3*(ig)+1];             \
                            zi##m = xyz[3*(ig)+2]; qi##m = q[(ig)]; }               \
            else { xi##m = 2.0e8f + (float)(ig) * 64.0f; yi##m = 0.0f;              \
                   zi##m = 0.0f; qi##m = 0.0f; }
        LOADI(0, ib) LOADI(1, ib + TJ) LOADI(2, ib + 2 * TJ) LOADI(3, ib + 3 * TJ)
        #undef LOADI
    }

    float acc0 = 0.0f, acc1 = 0.0f, acc2 = 0.0f, acc3 = 0.0f, accD = 0.0f;

    if (c >= RATIO) {
        // Full block: all 4 rows vs all TJ j.
        #pragma unroll 2
        for (int k = 0; k < TJ; k++) {
            float4 p = tile[k];
            PAIR(0) PAIR(1) PAIR(2) PAIR(3)
        }
    } else {
        // Partial block: rows m < c full, row m == c diagonal, rows m > c empty.
        if (c == 3) {
            #pragma unroll 2
            for (int k = 0; k < TJ; k++) {
                float4 p = tile[k];
                PAIR(0) PAIR(1) PAIR(2)
            }
        } else if (c == 2) {
            #pragma unroll 2
            for (int k = 0; k < TJ; k++) {
                float4 p = tile[k];
                PAIR(0) PAIR(1)
            }
        } else if (c == 1) {
            #pragma unroll 2
            for (int k = 0; k < TJ; k++) {
                float4 p = tile[k];
                PAIR(0)
            }
        }
        // Diagonal row (row index c): i is the t-th atom of this j-tile; j>i <=> k>t.
        float xd = (c == 0) ? xi0 : (c == 1) ? xi1 : (c == 2) ? xi2 : xi3;
        float yd = (c == 0) ? yi0 : (c == 1) ? yi1 : (c == 2) ? yi2 : yi3;
        float zd = (c == 0) ? zi0 : (c == 1) ? zi1 : (c == 2) ? zi2 : zi3;
        for (int k = t + 1; k < TJ; k++) {
            float4 p = tile[k];
            float dx = p.x - xd, dy = p.y - yd, dz = p.z - zd;
            float d2 = fmaf(dx, dx, fmaf(dy, dy, dz * dz));
            accD = fmaf(p.w, term_branchless(d2), accD);
        }
    }

    // qi hoisted out of inner loops.
    float qd = (c >= RATIO) ? 0.0f : (c == 0) ? qi0 : (c == 1) ? qi1 : (c == 2) ? qi2 : qi3;
    float accT = qi0 * acc0 + qi1 * acc1 + qi2 * acc2 + qi3 * acc3 + qd * accD;

    // Block reduction.
    #pragma unroll
    for (int off = 16; off > 0; off >>= 1)
        accT += __shfl_down_sync(0xFFFFFFFFu, accT, off);
    if ((t & 31) == 0) warpsum[t >> 5] = accT;
    __syncthreads();

    if (t == 0) {
        float sum = 0.0f;
        #pragma unroll
        for (int w = 0; w < TJ / 32; w++) sum += warpsum[w];
        g_partials[bid] = sum;
        __threadfence();
        int ticket = atomicAdd(&g_counter, 1);
        lastFlag = (ticket == nBlocks - 1) ? 1 : 0;
    }
    __syncthreads();

    if (lastFlag) {
        float a2 = 0.0f;
        for (int i = t; i < nBlocks; i += TJ)
            a2 += g_partials[i];
        #pragma unroll
        for (int off = 16; off > 0; off >>= 1)
            a2 += __shfl_down_sync(0xFFFFFFFFu, a2, off);
        if ((t & 31) == 0) warpsum[t >> 5] = a2;
        __syncthreads();
        if (t == 0) {
            float sum = 0.0f;
            #pragma unroll
            for (int w = 0; w < TJ / 32; w++) sum += warpsum[w];
            out[0] = sum * 332.0637f;   // KE_KCAL once
            g_counter = 0;              // reset for next graph replay
        }
    }
}

extern "C" void kernel_launch(void* const* d_in, const int* in_sizes, int n_in,
                              void* d_out, int out_size) {
    const float* q   = (const float*)d_in[0];
    const float* xyz = (const float*)d_in[1];
    float* out = (float*)d_out;

    int n  = in_sizes[0];
    int jT = (n + TJ - 1) / TJ;
    int iT = (n + TI - 1) / TI;
    int nBlocks = 0;
    for (int I = 0; I < iT; I++) {
        int cnt = jT - RATIO * I;
        if (cnt > 0) nBlocks += cnt;
    }
    if (nBlocks > MAX_BLOCKS) nBlocks = MAX_BLOCKS;

    elec_pair_kernel<<<nBlocks, TJ>>>(q, xyz, out, n, jT, nBlocks);
}

// round 6
// speedup vs baseline: 1.2857x; 1.0476x over previous
#include <cuda_runtime.h>

#define TJ 128          // j-tile = block threads (64 j-pairs)
#define ITILE 2         // i-rows per thread
#define TI (TJ * ITILE) // 256: i-tile span
#define MAX_BLOCKS 8192

typedef unsigned long long u64;

__device__ float g_partials[MAX_BLOCKS];
__device__ int   g_counter = 0;

// fs(d2) = 1 + s^2 * (A + B s + C s^2 + D s^3 + E s^4), s = sat((d2-9)/16)
// Exact ends: fs(d2<=9)=1, fs(d2>=25)=-8e-5~0. Max abs err ~0.02 in window.
#define FS_A  0.16122f
#define FS_B  (-16.875f)
#define FS_C  32.893f
#define FS_D  (-21.806f)
#define FS_E  4.6267f

// ---- f32x2 packed helpers (Blackwell packed fp32; ptxas won't emit these from C++) ----
__device__ __forceinline__ u64 f2pack(float lo, float hi) {
    u64 r; asm("mov.b64 %0,{%1,%2};" : "=l"(r) : "f"(lo), "f"(hi)); return r;
}
__device__ __forceinline__ void f2unpack(u64 v, float& lo, float& hi) {
    asm("mov.b64 {%0,%1},%2;" : "=f"(lo), "=f"(hi) : "l"(v));
}
__device__ __forceinline__ u64 f2add(u64 a, u64 b) {
    u64 d; asm("add.rn.f32x2 %0,%1,%2;" : "=l"(d) : "l"(a), "l"(b)); return d;
}
__device__ __forceinline__ u64 f2mul(u64 a, u64 b) {
    u64 d; asm("mul.rn.f32x2 %0,%1,%2;" : "=l"(d) : "l"(a), "l"(b)); return d;
}
__device__ __forceinline__ u64 f2fma(u64 a, u64 b, u64 c) {
    u64 d; asm("fma.rn.f32x2 %0,%1,%2,%3;" : "=l"(d) : "l"(a), "l"(b), "l"(c)); return d;
}

// Scalar term (diagonal rows only).
__device__ __forceinline__ float term_scalar(float d2) {
    float rinv = rsqrtf(d2);
    float s = __saturatef(fmaf(d2, 0.0625f, -0.5625f));
    float w = fmaf(FS_E, s, FS_D);
    w = fmaf(w, s, FS_C); w = fmaf(w, s, FS_B); w = fmaf(w, s, FS_A);
    float fs = fmaf(w, s * s, 1.0f);
    float isq = rsqrtf(d2 + 1.0f);
    return fmaf(fs, isq - rinv, rinv);
}

// Packed pair update: two j's vs one i-row. nx2/ny2/nz2 hold NEGATED j coords.
#define PAIR2(m)                                                             \
    {                                                                        \
        u64 dx = f2add(xi2##m, nx2);                                         \
        u64 dy = f2add(yi2##m, ny2);                                         \
        u64 dz = f2add(zi2##m, nz2);                                         \
        u64 d2p = f2fma(dx, dx, f2fma(dy, dy, f2mul(dz, dz)));               \
        float d2a, d2b; f2unpack(d2p, d2a, d2b);                             \
        float ra = rsqrtf(d2a), rb = rsqrtf(d2b);                            \
        float sa = __saturatef(fmaf(d2a, 0.0625f, -0.5625f));                \
        float sb = __saturatef(fmaf(d2b, 0.0625f, -0.5625f));                \
        u64 s2 = f2pack(sa, sb);                                             \
        u64 w = f2fma(cE, s2, cD);                                           \
        w = f2fma(w, s2, cC); w = f2fma(w, s2, cB); w = f2fma(w, s2, cA);    \
        u64 u2 = f2mul(s2, s2);                                              \
        u64 fs2 = f2fma(w, u2, cONE);                                        \
        float ia = rsqrtf(d2a + 1.0f), ib = rsqrtf(d2b + 1.0f);              \
        u64 diff2 = f2pack(ia - ra, ib - rb);                                \
        u64 rinv2 = f2pack(ra, rb);                                          \
        u64 term2 = f2fma(fs2, diff2, rinv2);                                \
        acc2##m = f2fma(wq2, term2, acc2##m);                                \
    }

__global__ __launch_bounds__(TJ)
void elec_pair_kernel(const float* __restrict__ q,
                      const float* __restrict__ xyz,
                      float* __restrict__ out,
                      int n, int jT, int nBlocks) {
    // bid -> (I, J): for i-tile I, valid j-tiles J = ITILE*I .. jT-1.
    const int bid = blockIdx.x;
    int I = 0, s = 0;
    while (bid >= s + (jT - ITILE * I)) { s += jT - ITILE * I; I++; }
    const int J = ITILE * I + (bid - s);
    const int c = J - ITILE * I;          // 0..1 partial/diagonal; >=2 full

    const int t = threadIdx.x;
    __shared__ ulonglong2 pkA[TJ / 2];    // {nx_2k,nx_2k+1 | ny_2k,ny_2k+1}
    __shared__ ulonglong2 pkB[TJ / 2];    // {nz_2k,nz_2k+1 |  q_2k, q_2k+1}
    __shared__ float warpsum[TJ / 32];
    __shared__ int lastFlag;

    // Stage j-tile: negated coords, pair-packed.
    {
        const int jg = J * TJ + t;
        float x, y, z, w;
        if (jg < n) { x = xyz[3 * jg]; y = xyz[3 * jg + 1]; z = xyz[3 * jg + 2]; w = q[jg]; }
        else        { x = 1.0e8f + (float)t * 64.0f; y = 0.0f; z = 0.0f; w = 0.0f; }
        float* fA = (float*)&pkA[t >> 1];
        float* fB = (float*)&pkB[t >> 1];
        fA[t & 1]       = -x;
        fA[2 + (t & 1)] = -y;
        fB[t & 1]       = -z;
        fB[2 + (t & 1)] = w;
    }
    __syncthreads();

    // Two i-rows per thread.
    const int ib = I * TI + t;
    float xi0, yi0, zi0, qi0, xi1, yi1, zi1, qi1;
    {
        #define LOADI(m, ig)                                                        \
            if ((ig) < n) { xi##m = xyz[3*(ig)]; yi##m = xyz[3*(ig)+1];             \
                            zi##m = xyz[3*(ig)+2]; qi##m = q[(ig)]; }               \
            else { xi##m = 2.0e8f + (float)(ig) * 64.0f; yi##m = 0.0f;              \
                   zi##m = 0.0f; qi##m = 0.0f; }
        LOADI(0, ib) LOADI(1, ib + TJ)
        #undef LOADI
    }

    // Hoisted packed constants and splats.
    const u64 cA = f2pack(FS_A, FS_A), cB = f2pack(FS_B, FS_B);
    const u64 cC = f2pack(FS_C, FS_C), cD = f2pack(FS_D, FS_D);
    const u64 cE = f2pack(FS_E, FS_E), cONE = f2pack(1.0f, 1.0f);
    const u64 xi20 = f2pack(xi0, xi0), yi20 = f2pack(yi0, yi0), zi20 = f2pack(zi0, zi0);
    const u64 xi21 = f2pack(xi1, xi1), yi21 = f2pack(yi1, yi1), zi21 = f2pack(zi1, zi1);

    u64 acc20 = 0ull, acc21 = 0ull;   // packed {0.0f,0.0f}
    float accD = 0.0f;

    if (c >= ITILE) {
        #pragma unroll 2
        for (int kp = 0; kp < TJ / 2; kp++) {
            ulonglong2 Av = pkA[kp];
            ulonglong2 Bv = pkB[kp];
            u64 nx2 = Av.x, ny2 = Av.y, nz2 = Bv.x, wq2 = Bv.y;
            PAIR2(0) PAIR2(1)
        }
    } else {
        if (c == 1) {
            #pragma unroll 2
            for (int kp = 0; kp < TJ / 2; kp++) {
                ulonglong2 Av = pkA[kp];
                ulonglong2 Bv = pkB[kp];
                u64 nx2 = Av.x, ny2 = Av.y, nz2 = Bv.x, wq2 = Bv.y;
                PAIR2(0)
            }
        }
        // Diagonal row (row index c): i = t-th atom of this j-tile; j > i <=> k > t.
        float xd = (c == 0) ? xi0 : xi1;
        float yd = (c == 0) ? yi0 : yi1;
        float zd = (c == 0) ? zi0 : zi1;
        const float* fA = (const float*)pkA;
        const float* fB = (const float*)pkB;
        for (int k = t + 1; k < TJ; k++) {
            int base = 4 * (k >> 1) + (k & 1);
            float dx = fA[base] + xd;          // (-xj) + xi
            float dy = fA[base + 2] + yd;
            float dz = fB[base] + zd;
            float wj = fB[base + 2];
            float d2 = fmaf(dx, dx, fmaf(dy, dy, dz * dz));
            accD = fmaf(wj, term_scalar(d2), accD);
        }
    }

    // Combine: qi hoisted.
    float a0l, a0h, a1l, a1h;
    f2unpack(acc20, a0l, a0h);
    f2unpack(acc21, a1l, a1h);
    float qd = (c >= ITILE) ? 0.0f : (c == 0) ? qi0 : qi1;
    float accT = qi0 * (a0l + a0h) + qi1 * (a1l + a1h) + qd * accD;

    // Block reduction.
    #pragma unroll
    for (int off = 16; off > 0; off >>= 1)
        accT += __shfl_down_sync(0xFFFFFFFFu, accT, off);
    if ((t & 31) == 0) warpsum[t >> 5] = accT;
    __syncthreads();

    if (t == 0) {
        float sum = 0.0f;
        #pragma unroll
        for (int w = 0; w < TJ / 32; w++) sum += warpsum[w];
        g_partials[bid] = sum;
        __threadfence();
        int ticket = atomicAdd(&g_counter, 1);
        lastFlag = (ticket == nBlocks - 1) ? 1 : 0;
    }
    __syncthreads();

    if (lastFlag) {
        float a2 = 0.0f;
        for (int i = t; i < nBlocks; i += TJ)
            a2 += g_partials[i];
        #pragma unroll
        for (int off = 16; off > 0; off >>= 1)
            a2 += __shfl_down_sync(0xFFFFFFFFu, a2, off);
        if ((t & 31) == 0) warpsum[t >> 5] = a2;
        __syncthreads();
        if (t == 0) {
            float sum = 0.0f;
            #pragma unroll
            for (int w = 0; w < TJ / 32; w++) sum += warpsum[w];
            out[0] = sum * 332.0637f;
            g_counter = 0;
        }
    }
}

extern "C" void kernel_launch(void* const* d_in, const int* in_sizes, int n_in,
                              void* d_out, int out_size) {
    const float* q   = (const float*)d_in[0];
    const float* xyz = (const float*)d_in[1];
    float* out = (float*)d_out;

    int n  = in_sizes[0];
    int jT = (n + TJ - 1) / TJ;
    int iT = (n + TI - 1) / TI;
    int nBlocks = 0;
    for (int I = 0; I < iT; I++) {
        int cnt = jT - ITILE * I;
        if (cnt > 0) nBlocks += cnt;
    }
    if (nBlocks > MAX_BLOCKS) nBlocks = MAX_BLOCKS;

    elec_pair_kernel<<<nBlocks, TJ>>>(q, xyz, out, n, jT, nBlocks);
}

// round 7
// speedup vs baseline: 1.4961x; 1.1636x over previous
#include <cuda_runtime.h>

#define TJ 128          // j-tile = block threads
#define ITILE 4         // i-rows per thread
#define TI (TJ * ITILE) // 512: i-tile span
#define MAX_BLOCKS 8192

__device__ float g_partials[MAX_BLOCKS];
__device__ int   g_counter = 0;   // self-resetting arrival counter

// fs(d2) = 1 + s^2 * (A + B s + C s^2 + D s^3),  s = sat((d2-9)/16)
// Cubic refit; P(1) = -1 exactly -> fs(r>=5) = 0, fs(d2<=9) = 1 (saturate).
#define FS_A  1.733f
#define FS_B  (-23.203f)
#define FS_C  38.001f
#define FS_D  (-17.531f)

// Pair term using dot-form d2. base = Ri + Rj (precomputed partial).
__device__ __forceinline__ float term_d2(float d2) {
    float rinv = rsqrtf(d2);
    float s = __saturatef(fmaf(d2, 0.0625f, -0.5625f));
    float w = fmaf(fmaf(FS_D, s, FS_C), s, FS_B);
    w = fmaf(w, s, FS_A);
    float u = s * s;
    float isq = rsqrtf(d2 + 1.0f);
    float g = isq - rinv;
    float fs = fmaf(u, w, 1.0f);
    return fmaf(fs, g, rinv);
}

// One pair: i-row m vs j-atom (xj,yj,zj,qj,Rj). nxm = -2*xi etc.
#define PAIR(m)                                                              \
    {                                                                        \
        float base = Ri##m + Rj;                                             \
        float d2 = fmaf(nz##m, p.z, fmaf(ny##m, p.y, fmaf(nx##m, p.x, base)));\
        acc##m = fmaf(p.w, term_d2(d2), acc##m);                             \
    }

__global__ __launch_bounds__(TJ)
void elec_pair_kernel(const float* __restrict__ q,
                      const float* __restrict__ xyz,
                      float* __restrict__ out,
                      int n, int jT, int nFull, int nBlocks) {
    // Heavy-first mapping: bid < nFull -> full blocks (J >= ITILE*(I+1)),
    // bid >= nFull -> partial/diagonal blocks (J = ITILE*I + c, c in [0,ITILE)).
    const int bid = blockIdx.x;
    int I, J, c;
    if (bid < nFull) {
        int s = 0; I = 0;
        // full-count for tile I: jT - ITILE*(I+1)  (>= 0)
        while (bid >= s + (jT - ITILE * (I + 1))) { s += jT - ITILE * (I + 1); I++; }
        J = ITILE * (I + 1) + (bid - s);
        c = ITILE;   // marker: full
    } else {
        int p = bid - nFull;
        I = p / ITILE;
        c = p - I * ITILE;
        J = ITILE * I + c;
    }

    const int t = threadIdx.x;
    __shared__ float4 tile[TJ];       // {xj, yj, zj, qj}
    __shared__ float  tileR[TJ];      // |rj|^2
    __shared__ float  warpsum[TJ / 32];
    __shared__ int    lastFlag;

    // Stage j-tile.
    {
        const int jg = J * TJ + t;
        float x, y, z, w;
        if (jg < n) { x = xyz[3 * jg]; y = xyz[3 * jg + 1]; z = xyz[3 * jg + 2]; w = q[jg]; }
        else        { x = 1.0e6f + (float)t * 64.0f; y = 0.0f; z = 0.0f; w = 0.0f; }
        tile[t]  = make_float4(x, y, z, w);
        tileR[t] = fmaf(x, x, fmaf(y, y, z * z));
    }
    __syncthreads();

    // Four i-rows per thread: store (-2x, -2y, -2z, |r|^2, q).
    const int ib = I * TI + t;
    float nx0, ny0, nz0, Ri0, qi0, nx1, ny1, nz1, Ri1, qi1;
    float nx2, ny2, nz2, Ri2, qi2, nx3, ny3, nz3, Ri3, qi3;
    {
        #define LOADI(m, ig)                                                          \
            { float x, y, z;                                                          \
              if ((ig) < n) { x = xyz[3*(ig)]; y = xyz[3*(ig)+1];                     \
                              z = xyz[3*(ig)+2]; qi##m = q[(ig)]; }                   \
              else { x = 2.0e6f + (float)(ig) * 64.0f; y = 0.0f; z = 0.0f;            \
                     qi##m = 0.0f; }                                                  \
              nx##m = -2.0f * x; ny##m = -2.0f * y; nz##m = -2.0f * z;                \
              Ri##m = fmaf(x, x, fmaf(y, y, z * z)); }
        LOADI(0, ib) LOADI(1, ib + TJ) LOADI(2, ib + 2 * TJ) LOADI(3, ib + 3 * TJ)
        #undef LOADI
    }

    float acc0 = 0.0f, acc1 = 0.0f, acc2 = 0.0f, acc3 = 0.0f, accD = 0.0f;

    if (c >= ITILE) {
        // Full block: 4 rows vs all TJ j.
        #pragma unroll 4
        for (int k = 0; k < TJ; k++) {
            float4 p = tile[k];
            float Rj = tileR[k];
            PAIR(0) PAIR(1) PAIR(2) PAIR(3)
        }
    } else {
        // Partial: rows m < c full, row c diagonal, rows > c empty.
        if (c == 3) {
            #pragma unroll 4
            for (int k = 0; k < TJ; k++) {
                float4 p = tile[k]; float Rj = tileR[k];
                PAIR(0) PAIR(1) PAIR(2)
            }
        } else if (c == 2) {
            #pragma unroll 4
            for (int k = 0; k < TJ; k++) {
                float4 p = tile[k]; float Rj = tileR[k];
                PAIR(0) PAIR(1)
            }
        } else if (c == 1) {
            #pragma unroll 4
            for (int k = 0; k < TJ; k++) {
                float4 p = tile[k]; float Rj = tileR[k];
                PAIR(0)
            }
        }
        // Diagonal row c: i is the t-th atom of this j-tile; j > i <=> k > t.
        float nxd = (c == 0) ? nx0 : (c == 1) ? nx1 : (c == 2) ? nx2 : nx3;
        float nyd = (c == 0) ? ny0 : (c == 1) ? ny1 : (c == 2) ? ny2 : ny3;
        float nzd = (c == 0) ? nz0 : (c == 1) ? nz1 : (c == 2) ? nz2 : nz3;
        float Rid = (c == 0) ? Ri0 : (c == 1) ? Ri1 : (c == 2) ? Ri2 : Ri3;
        for (int k = t + 1; k < TJ; k++) {
            float4 p = tile[k];
            float Rj = tileR[k];
            float base = Rid + Rj;
            float d2 = fmaf(nzd, p.z, fmaf(nyd, p.y, fmaf(nxd, p.x, base)));
            accD = fmaf(p.w, term_d2(d2), accD);
        }
    }

    // qi hoisted out of inner loops.
    float qd = (c >= ITILE) ? 0.0f : (c == 0) ? qi0 : (c == 1) ? qi1 : (c == 2) ? qi2 : qi3;
    float accT = qi0 * acc0 + qi1 * acc1 + qi2 * acc2 + qi3 * acc3 + qd * accD;

    // Block reduction.
    #pragma unroll
    for (int off = 16; off > 0; off >>= 1)
        accT += __shfl_down_sync(0xFFFFFFFFu, accT, off);
    if ((t & 31) == 0) warpsum[t >> 5] = accT;
    __syncthreads();

    if (t == 0) {
        float sum = 0.0f;
        #pragma unroll
        for (int w = 0; w < TJ / 32; w++) sum += warpsum[w];
        g_partials[bid] = sum;
        __threadfence();
        int ticket = atomicAdd(&g_counter, 1);
        lastFlag = (ticket == nBlocks - 1) ? 1 : 0;
    }
    __syncthreads();

    if (lastFlag) {
        float a2 = 0.0f;
        for (int i = t; i < nBlocks; i += TJ)
            a2 += g_partials[i];
        #pragma unroll
        for (int off = 16; off > 0; off >>= 1)
            a2 += __shfl_down_sync(0xFFFFFFFFu, a2, off);
        if ((t & 31) == 0) warpsum[t >> 5] = a2;
        __syncthreads();
        if (t == 0) {
            float sum = 0.0f;
            #pragma unroll
            for (int w = 0; w < TJ / 32; w++) sum += warpsum[w];
            out[0] = sum * 332.0637f;   // KE_KCAL once
            g_counter = 0;              // reset for next graph replay
        }
    }
}

extern "C" void kernel_launch(void* const* d_in, const int* in_sizes, int n_in,
                              void* d_out, int out_size) {
    const float* q   = (const float*)d_in[0];
    const float* xyz = (const float*)d_in[1];
    float* out = (float*)d_out;

    int n  = in_sizes[0];
    int jT = (n + TJ - 1) / TJ;
    int iT = (n + TI - 1) / TI;
    int nFull = 0, nPart = 0;
    for (int I = 0; I < iT; I++) {
        int f = jT - ITILE * (I + 1);
        if (f > 0) nFull += f;
        int pmax = jT - ITILE * I;
        nPart += (pmax < ITILE) ? pmax : ITILE;
    }
    int nBlocks = nFull + nPart;
    if (nBlocks > MAX_BLOCKS) nBlocks = MAX_BLOCKS;

    elec_pair_kernel<<<nBlocks, TJ>>>(q, xyz, out, n, jT, nFull, nBlocks);
}

// round 8
// speedup vs baseline: 1.5868x; 1.0606x over previous
#include <cuda_runtime.h>

#define TJ 128          // j-tile = block threads
#define ITILE 4         // i-rows per thread
#define TI (TJ * ITILE) // 512: i-tile span
#define MAX_BLOCKS 8192

__device__ float g_partials[MAX_BLOCKS];
__device__ int   g_counter = 0;   // self-resetting arrival counter

// fs(d2) = 1 + s^2 * P(s), P(s) = A + B s + C s^2 + D s^3, s = sat((d2-9)/16)
// P(1) = -1 exactly -> fs = 0 for d2 >= 25 (makes untaken-lane correction 0).
#define FS_A  1.733f
#define FS_B  (-23.203f)
#define FS_C  38.001f
#define FS_D  (-17.531f)

// Branchless full term (diagonal rows only; lane-divergent trip counts there).
__device__ __forceinline__ float term_d2(float d2) {
    float rinv = rsqrtf(d2);
    float s = __saturatef(fmaf(d2, 0.0625f, -0.5625f));
    float w = fmaf(fmaf(fmaf(FS_D, s, FS_C), s, FS_B), s, FS_A);
    float u = s * s;
    float isq = rsqrtf(d2 + 1.0f);
    float g = isq - rinv;
    float fs = fmaf(u, w, 1.0f);
    return fmaf(fs, g, rinv);
}

// Pair update: unconditional bare Coulomb + warp-uniform rare correction.
// Legal only in loops with warp-uniform trip counts.
#define PAIR(m)                                                               \
    {                                                                         \
        float d2 = fmaf(nz##m, p.z, fmaf(ny##m, p.y,                          \
                     fmaf(nx##m, p.x, Ri##m + Rj)));                          \
        float rinv = rsqrtf(d2);                                              \
        acc##m = fmaf(p.w, rinv, acc##m);                                     \
        if (__any_sync(0xFFFFFFFFu, d2 < 25.0f)) {                            \
            float s = __saturatef(fmaf(d2, 0.0625f, -0.5625f));               \
            float w = fmaf(fmaf(fmaf(FS_D, s, FS_C), s, FS_B), s, FS_A);      \
            float u = s * s;                                                  \
            float fsw = u * w;               /* fs_full - 1 */                \
            float isq = rsqrtf(d2 + 1.0f);                                    \
            float g = isq - rinv;                                             \
            float corr = fmaf(fsw, g, g);    /* (1 + u*w) * g */              \
            acc##m = fmaf(p.w, corr, acc##m);                                 \
        }                                                                     \
    }

__global__ __launch_bounds__(TJ)
void elec_pair_kernel(const float* __restrict__ q,
                      const float* __restrict__ xyz,
                      float* __restrict__ out,
                      int n, int jT, int nFull, int nBlocks) {
    // Heavy-first mapping: bid < nFull -> full blocks, else partial/diagonal.
    const int bid = blockIdx.x;
    int I, J, c;
    if (bid < nFull) {
        int s = 0; I = 0;
        while (bid >= s + (jT - ITILE * (I + 1))) { s += jT - ITILE * (I + 1); I++; }
        J = ITILE * (I + 1) + (bid - s);
        c = ITILE;   // full
    } else {
        int p = bid - nFull;
        I = p / ITILE;
        c = p - I * ITILE;
        J = ITILE * I + c;
    }

    const int t = threadIdx.x;
    __shared__ float4 tile[TJ];       // {xj, yj, zj, qj}
    __shared__ float  tileR[TJ];      // |rj|^2
    __shared__ float  warpsum[TJ / 32];
    __shared__ int    lastFlag;

    // Stage j-tile.
    {
        const int jg = J * TJ + t;
        float x, y, z, w;
        if (jg < n) { x = xyz[3 * jg]; y = xyz[3 * jg + 1]; z = xyz[3 * jg + 2]; w = q[jg]; }
        else        { x = 1.0e6f + (float)t * 64.0f; y = 0.0f; z = 0.0f; w = 0.0f; }
        tile[t]  = make_float4(x, y, z, w);
        tileR[t] = fmaf(x, x, fmaf(y, y, z * z));
    }
    __syncthreads();

    // Four i-rows per thread: (-2x, -2y, -2z, |r|^2, q).
    const int ib = I * TI + t;
    float nx0, ny0, nz0, Ri0, qi0, nx1, ny1, nz1, Ri1, qi1;
    float nx2, ny2, nz2, Ri2, qi2, nx3, ny3, nz3, Ri3, qi3;
    {
        #define LOADI(m, ig)                                                          \
            { float x, y, z;                                                          \
              if ((ig) < n) { x = xyz[3*(ig)]; y = xyz[3*(ig)+1];                     \
                              z = xyz[3*(ig)+2]; qi##m = q[(ig)]; }                   \
              else { x = 2.0e6f + (float)(ig) * 64.0f; y = 0.0f; z = 0.0f;            \
                     qi##m = 0.0f; }                                                  \
              nx##m = -2.0f * x; ny##m = -2.0f * y; nz##m = -2.0f * z;                \
              Ri##m = fmaf(x, x, fmaf(y, y, z * z)); }
        LOADI(0, ib) LOADI(1, ib + TJ) LOADI(2, ib + 2 * TJ) LOADI(3, ib + 3 * TJ)
        #undef LOADI
    }

    float acc0 = 0.0f, acc1 = 0.0f, acc2 = 0.0f, acc3 = 0.0f, accD = 0.0f;

    if (c >= ITILE) {
        #pragma unroll 4
        for (int k = 0; k < TJ; k++) {
            float4 p = tile[k];
            float Rj = tileR[k];
            PAIR(0) PAIR(1) PAIR(2) PAIR(3)
        }
    } else {
        if (c == 3) {
            #pragma unroll 4
            for (int k = 0; k < TJ; k++) {
                float4 p = tile[k]; float Rj = tileR[k];
                PAIR(0) PAIR(1) PAIR(2)
            }
        } else if (c == 2) {
            #pragma unroll 4
            for (int k = 0; k < TJ; k++) {
                float4 p = tile[k]; float Rj = tileR[k];
                PAIR(0) PAIR(1)
            }
        } else if (c == 1) {
            #pragma unroll 4
            for (int k = 0; k < TJ; k++) {
                float4 p = tile[k]; float Rj = tileR[k];
                PAIR(0)
            }
        }
        // Diagonal row c (lane-dependent trip count -> branchless term).
        float nxd = (c == 0) ? nx0 : (c == 1) ? nx1 : (c == 2) ? nx2 : nx3;
        float nyd = (c == 0) ? ny0 : (c == 1) ? ny1 : (c == 2) ? ny2 : ny3;
        float nzd = (c == 0) ? nz0 : (c == 1) ? nz1 : (c == 2) ? nz2 : nz3;
        float Rid = (c == 0) ? Ri0 : (c == 1) ? Ri1 : (c == 2) ? Ri2 : Ri3;
        for (int k = t + 1; k < TJ; k++) {
            float4 p = tile[k];
            float Rj = tileR[k];
            float d2 = fmaf(nzd, p.z, fmaf(nyd, p.y, fmaf(nxd, p.x, Rid + Rj)));
            accD = fmaf(p.w, term_d2(d2), accD);
        }
    }

    float qd = (c >= ITILE) ? 0.0f : (c == 0) ? qi0 : (c == 1) ? qi1 : (c == 2) ? qi2 : qi3;
    float accT = qi0 * acc0 + qi1 * acc1 + qi2 * acc2 + qi3 * acc3 + qd * accD;

    // Block reduction.
    #pragma unroll
    for (int off = 16; off > 0; off >>= 1)
        accT += __shfl_down_sync(0xFFFFFFFFu, accT, off);
    if ((t & 31) == 0) warpsum[t >> 5] = accT;
    __syncthreads();

    if (t == 0) {
        float sum = 0.0f;
        #pragma unroll
        for (int w = 0; w < TJ / 32; w++) sum += warpsum[w];
        g_partials[bid] = sum;
        __threadfence();
        int ticket = atomicAdd(&g_counter, 1);
        lastFlag = (ticket == nBlocks - 1) ? 1 : 0;
    }
    __syncthreads();

    if (lastFlag) {
        float a2 = 0.0f;
        for (int i = t; i < nBlocks; i += TJ)
            a2 += g_partials[i];
        #pragma unroll
        for (int off = 16; off > 0; off >>= 1)
            a2 += __shfl_down_sync(0xFFFFFFFFu, a2, off);
        if ((t & 31) == 0) warpsum[t >> 5] = a2;
        __syncthreads();
        if (t == 0) {
            float sum = 0.0f;
            #pragma unroll
            for (int w = 0; w < TJ / 32; w++) sum += warpsum[w];
            out[0] = sum * 332.0637f;   // KE_KCAL once
            g_counter = 0;              // reset for next graph replay
        }
    }
}

extern "C" void kernel_launch(void* const* d_in, const int* in_sizes, int n_in,
                              void* d_out, int out_size) {
    const float* q   = (const float*)d_in[0];
    const float* xyz = (const float*)d_in[1];
    float* out = (float*)d_out;

    int n  = in_sizes[0];
    int jT = (n + TJ - 1) / TJ;
    int iT = (n + TI - 1) / TI;
    int nFull = 0, nPart = 0;
    for (int I = 0; I < iT; I++) {
        int f = jT - ITILE * (I + 1);
        if (f > 0) nFull += f;
        int pmax = jT - ITILE * I;
        nPart += (pmax < ITILE) ? pmax : ITILE;
    }
    int nBlocks = nFull + nPart;
    if (nBlocks > MAX_BLOCKS) nBlocks = MAX_BLOCKS;

    elec_pair_kernel<<<nBlocks, TJ>>>(q, xyz, out, n, jT, nFull, nBlocks);
}